// round 12
// baseline (speedup 1.0000x reference)
#include <cuda_runtime.h>
#include <cuda_fp16.h>
#include <math.h>
#include <stdint.h>

#define NB 8
#define CC 128
#define LL 4096
#define NL (NB * LL)          // 32768
#define LSPLIT 8
#define EPS_BAND 1e-5f

// GEMM tile
#define TM 128
#define TN 256
#define SSH 136                                   // padded row stride in halves
#define A_HALFS (TM * SSH)                        // 17408
#define B_HALFS (TN * SSH)                        // 34816
#define SMEM_BYTES ((A_HALFS + B_HALFS) * 2)      // 104448

// ---------------- scratch (device globals; device-code references only) ------
__device__ float  g_ymu[CC];
__device__ __half g_xh[(size_t)NB * LL * CC];          // K-major [n][l][c] fp16
__device__ __half g_yh[(size_t)NB * LL * CC];
__device__ __half g_cosh[(size_t)NB * LL * LL];        // 268 MB fp16 cos
__device__ float  g_alpha[NL];
__device__ float  g_off[NL];
__device__ float  g_colpart[(size_t)LSPLIT * NB * LL];
__device__ float  g_loss_n[NB];

// ---------------- asm helpers --------------------------------------------------
__device__ __forceinline__ uint32_t smem_u32(const void* p) {
    uint32_t a;
    asm("{ .reg .u64 t; cvta.to.shared.u64 t, %1; cvt.u32.u64 %0, t; }" : "=r"(a) : "l"(p));
    return a;
}
#define CP_ASYNC16(sa, gp) \
    asm volatile("cp.async.cg.shared.global [%0], [%1], 16;" :: "r"(sa), "l"(gp))
#define CP_COMMIT() asm volatile("cp.async.commit_group;" ::: "memory")

#define LDSM4(R, addr) \
    asm volatile("ldmatrix.sync.aligned.m8n8.x4.shared.b16 {%0,%1,%2,%3}, [%4];" \
        : "=r"((R)[0]), "=r"((R)[1]), "=r"((R)[2]), "=r"((R)[3]) : "r"(addr))

__device__ __forceinline__ void mma_f16(float* c, const uint32_t* a, const uint32_t* b) {
    asm volatile(
        "mma.sync.aligned.m16n8k16.row.col.f32.f16.f16.f32 "
        "{%0,%1,%2,%3}, {%4,%5,%6,%7}, {%8,%9}, {%0,%1,%2,%3};"
        : "+f"(c[0]), "+f"(c[1]), "+f"(c[2]), "+f"(c[3])
        : "r"(a[0]), "r"(a[1]), "r"(a[2]), "r"(a[3]), "r"(b[0]), "r"(b[1]));
}

__device__ __forceinline__ float fast_exp(float x) {
    float y = x * 1.4426950408889634f;
    float t = y + 12582912.0f;
    int   n = __float_as_int(t) - 0x4B400000;
    float f = y - (t - 12582912.0f);
    float p =            1.3333558146e-3f;
    p = fmaf(p, f, 9.6181291071e-3f);
    p = fmaf(p, f, 5.5504108664e-2f);
    p = fmaf(p, f, 2.4022650696e-1f);
    p = fmaf(p, f, 6.9314718056e-1f);
    p = fmaf(p, f, 1.0f);
    return __int_as_float(__float_as_int(p) + (n << 23));
}

__device__ __forceinline__ float block_reduce_sum_256(float v) {
    __shared__ float sh[8];
    int lane = threadIdx.x & 31, w = threadIdx.x >> 5;
    #pragma unroll
    for (int o = 16; o; o >>= 1) v += __shfl_xor_sync(0xffffffffu, v, o);
    if (lane == 0) sh[w] = v;
    __syncthreads();
    if (w == 0) {
        v = (lane < 8) ? sh[lane] : 0.f;
        #pragma unroll
        for (int o = 4; o; o >>= 1) v += __shfl_xor_sync(0xffffffffu, v, o);
    }
    return v;
}
__device__ __forceinline__ float block_reduce_max_256(float v) {
    __shared__ float shm[8];
    int lane = threadIdx.x & 31, w = threadIdx.x >> 5;
    #pragma unroll
    for (int o = 16; o; o >>= 1) v = fmaxf(v, __shfl_xor_sync(0xffffffffu, v, o));
    if (lane == 0) shm[w] = v;
    __syncthreads();
    if (w == 0) {
        v = (lane < 8) ? shm[lane] : -INFINITY;
        #pragma unroll
        for (int o = 4; o; o >>= 1) v = fmaxf(v, __shfl_xor_sync(0xffffffffu, v, o));
    }
    return v;
}

// ---------------- kernels ------------------------------------------------------

__global__ __launch_bounds__(256) void ymu_kernel(const float* __restrict__ y) {
    int c = blockIdx.x;
    float s = 0.f;
    for (int i = threadIdx.x; i < NB * LL; i += 256) {
        int n = i >> 12, l = i & (LL - 1);
        s += y[(size_t)n * CC * LL + (size_t)c * LL + l];
    }
    s = block_reduce_sum_256(s);
    if (threadIdx.x == 0) g_ymu[c] = s * (1.0f / (NB * LL));
}

// Center + L2-normalize; K-major [n][l][c] fp16 output.
__global__ __launch_bounds__(256) void normalize_kernel(const float* __restrict__ src,
                                                        int dst_sel) {
    __half* __restrict__ dst = dst_sel ? g_yh : g_xh;
    __shared__ float mu[CC];
    if (threadIdx.x < CC) mu[threadIdx.x] = g_ymu[threadIdx.x];
    __syncthreads();
    int idx = blockIdx.x * 256 + threadIdx.x;  // n*L + l
    int n = idx >> 12, l = idx & (LL - 1);
    size_t base = (size_t)n * CC * LL + l;
    float ss = 0.f;
    #pragma unroll 8
    for (int c = 0; c < CC; c++) {
        float v = src[base + (size_t)c * LL] - mu[c];
        ss += v * v;
    }
    float r = 1.0f / fmaxf(sqrtf(ss), 1e-12f);
    uint4* drow = (uint4*)(dst + ((size_t)n * LL + l) * CC);
    #pragma unroll 2
    for (int c0 = 0; c0 < CC; c0 += 8) {
        __half2 p0 = __floats2half2_rn((src[base + (size_t)(c0 + 0) * LL] - mu[c0 + 0]) * r,
                                       (src[base + (size_t)(c0 + 1) * LL] - mu[c0 + 1]) * r);
        __half2 p1 = __floats2half2_rn((src[base + (size_t)(c0 + 2) * LL] - mu[c0 + 2]) * r,
                                       (src[base + (size_t)(c0 + 3) * LL] - mu[c0 + 3]) * r);
        __half2 p2 = __floats2half2_rn((src[base + (size_t)(c0 + 4) * LL] - mu[c0 + 4]) * r,
                                       (src[base + (size_t)(c0 + 5) * LL] - mu[c0 + 5]) * r);
        __half2 p3 = __floats2half2_rn((src[base + (size_t)(c0 + 6) * LL] - mu[c0 + 6]) * r,
                                       (src[base + (size_t)(c0 + 7) * LL] - mu[c0 + 7]) * r);
        uint4 o;
        o.x = *(uint32_t*)&p0; o.y = *(uint32_t*)&p1;
        o.z = *(uint32_t*)&p2; o.w = *(uint32_t*)&p3;
        drow[c0 >> 3] = o;
    }
}

// fp16 mma.sync GEMM: TM x TN tile, K=128 in 4 cp.async-pipelined K=32 stages.
// ldmatrix fragment loads; direct half2 STG epilogue.
__global__ __launch_bounds__(512, 1) void gemm_cos_mma() {
    extern __shared__ __half smh[];
    uint32_t sbase = smem_u32(smh);
    int tid = threadIdx.x;
    int w = tid >> 5, lane = tid & 31;
    int g = lane >> 2, t = lane & 3;
    int wm = w & 3, wn = w >> 2;
    int n = blockIdx.z, l0 = blockIdx.y * TM, m0 = blockIdx.x * TN;

    const __half* Agp = g_xh + ((size_t)n * LL + l0) * CC;
    const __half* Bgp = g_yh + ((size_t)n * LL + m0) * CC;

    // Issue all 4 K-stages as cp.async groups (stage s = K cols [32s, 32s+32)).
    #pragma unroll
    for (int s = 0; s < 4; s++) {
        {   // A: 128 rows x 4 chunks = 512 chunks -> 1 iter
            int r = tid >> 2, q = tid & 3;
            uint32_t sa = sbase + (uint32_t)(r * SSH + s * 32 + q * 8) * 2;
            CP_ASYNC16(sa, Agp + r * CC + s * 32 + q * 8);
        }
        #pragma unroll
        for (int it = 0; it < 2; it++) {  // B: 256 rows x 4 chunks = 1024 chunks
            int id = tid + it * 512; int r = id >> 2, q = id & 3;
            uint32_t sa = sbase + (uint32_t)(A_HALFS + r * SSH + s * 32 + q * 8) * 2;
            CP_ASYNC16(sa, Bgp + r * CC + s * 32 + q * 8);
        }
        CP_COMMIT();
    }

    // ldmatrix per-lane base addresses (byte).
    uint32_t a_base = sbase + (uint32_t)((wm * 32 + ((lane >> 3) & 1) * 8 + (lane & 7)) * SSH
                                         + ((lane >> 4) & 1) * 8) * 2;
    uint32_t b_base = sbase + (uint32_t)(A_HALFS
                                         + (wn * 64 + ((lane >> 4) & 1) * 8 + (lane & 7)) * SSH
                                         + ((lane >> 3) & 1) * 8) * 2;

    float acc[2][8][4];
    #pragma unroll
    for (int mt = 0; mt < 2; mt++)
        #pragma unroll
        for (int nt = 0; nt < 8; nt++)
            #pragma unroll
            for (int j = 0; j < 4; j++) acc[mt][nt][j] = 0.f;

    #pragma unroll
    for (int s = 0; s < 4; s++) {
        if      (s == 0) asm volatile("cp.async.wait_group 3;" ::: "memory");
        else if (s == 1) asm volatile("cp.async.wait_group 2;" ::: "memory");
        else if (s == 2) asm volatile("cp.async.wait_group 1;" ::: "memory");
        else             asm volatile("cp.async.wait_group 0;" ::: "memory");
        __syncthreads();
        #pragma unroll
        for (int k2 = 0; k2 < 2; k2++) {
            int ks = s * 2 + k2;               // k16 chunk; byte col offset = ks*32
            uint32_t a[2][4], bb[4][4];
            #pragma unroll
            for (int mt = 0; mt < 2; mt++)
                LDSM4(a[mt], a_base + (uint32_t)(mt * 16 * SSH * 2 + ks * 32));
            #pragma unroll
            for (int np = 0; np < 4; np++)
                LDSM4(bb[np], b_base + (uint32_t)(np * 16 * SSH * 2 + ks * 32));
            #pragma unroll
            for (int mt = 0; mt < 2; mt++)
                #pragma unroll
                for (int np = 0; np < 4; np++) {
                    mma_f16(acc[mt][2 * np],     a[mt], &bb[np][0]);
                    mma_f16(acc[mt][2 * np + 1], a[mt], &bb[np][2]);
                }
        }
    }

    // Direct fp16 store: h01 -> (row g, col 2t), h23 -> (row g+8, col 2t).
    __half* Cp = g_cosh + (size_t)n * LL * LL;
    #pragma unroll
    for (int mt = 0; mt < 2; mt++) {
        int r0 = l0 + wm * 32 + mt * 16 + g;
        #pragma unroll
        for (int nt = 0; nt < 8; nt++) {
            int col = m0 + wn * 64 + nt * 8 + 2 * t;
            __half2 h01 = __floats2half2_rn(acc[mt][nt][0], acc[mt][nt][1]);
            __half2 h23 = __floats2half2_rn(acc[mt][nt][2], acc[mt][nt][3]);
            *(__half2*)(Cp + (size_t)r0 * LL + col)       = h01;
            *(__half2*)(Cp + (size_t)(r0 + 8) * LL + col) = h23;
        }
    }
}

// Per row: rowmax -> alpha; Z = sum exp(alpha*(cos-1)); fp16 row read.
__global__ __launch_bounds__(256) void row_pass_kernel() {
    __shared__ float s_bcast;
    int row = blockIdx.x;  // n*L + l
    const uint4* cr = (const uint4*)(g_cosh + (size_t)row * LL);
    int t = threadIdx.x;

    uint4 u[2];
    u[0] = cr[t * 2];
    u[1] = cr[t * 2 + 1];

    float2 f[8];
    #pragma unroll
    for (int i = 0; i < 2; i++) {
        f[i * 4 + 0] = __half22float2(*(__half2*)&u[i].x);
        f[i * 4 + 1] = __half22float2(*(__half2*)&u[i].y);
        f[i * 4 + 2] = __half22float2(*(__half2*)&u[i].z);
        f[i * 4 + 3] = __half22float2(*(__half2*)&u[i].w);
    }
    float mx = -INFINITY;
    #pragma unroll
    for (int i = 0; i < 8; i++) mx = fmaxf(mx, fmaxf(f[i].x, f[i].y));
    mx = block_reduce_max_256(mx);
    if (threadIdx.x == 0) s_bcast = mx;
    __syncthreads();
    float rowmax = s_bcast;

    float dmin  = 1.0f - rowmax;
    float alpha = 2.0f / (dmin + EPS_BAND);

    float s = 0.f;
    #pragma unroll
    for (int i = 0; i < 8; i++) {
        s += fast_exp(alpha * (f[i].x - 1.0f));
        s += fast_exp(alpha * (f[i].y - 1.0f));
    }
    s = block_reduce_sum_256(s);
    if (threadIdx.x == 0) {
        g_alpha[row] = alpha;
        g_off[row]   = -alpha - logf(s);
    }
}

// Column pass over fp16 cos: partial max of (alpha_l*cos + off_l); uint4/thread.
__global__ __launch_bounds__(256) void col_pass_kernel() {
    int n = blockIdx.z;
    int m8 = blockIdx.x * 256 + threadIdx.x;       // uint4 index; grid.x = LL/2048
    int lbeg = blockIdx.y * (LL / LSPLIT);
    __shared__ float sA[128], sO[128];
    const uint4* Cp = (const uint4*)(g_cosh + (size_t)n * LL * LL);
    float best[8];
    #pragma unroll
    for (int j = 0; j < 8; j++) best[j] = -INFINITY;

    for (int c = 0; c < (LL / LSPLIT) / 128; c++) {
        int lb = lbeg + c * 128;
        __syncthreads();
        if (threadIdx.x < 128) {
            sA[threadIdx.x] = g_alpha[n * LL + lb + threadIdx.x];
            sO[threadIdx.x] = g_off[n * LL + lb + threadIdx.x];
        }
        __syncthreads();
        #pragma unroll 4
        for (int li = 0; li < 128; li++) {
            uint4 v = Cp[(size_t)(lb + li) * (LL / 8) + m8];
            float a = sA[li], o = sO[li];
            float2 f0 = __half22float2(*(__half2*)&v.x);
            float2 f1 = __half22float2(*(__half2*)&v.y);
            float2 f2 = __half22float2(*(__half2*)&v.z);
            float2 f3 = __half22float2(*(__half2*)&v.w);
            best[0] = fmaxf(best[0], fmaf(a, f0.x, o));
            best[1] = fmaxf(best[1], fmaf(a, f0.y, o));
            best[2] = fmaxf(best[2], fmaf(a, f1.x, o));
            best[3] = fmaxf(best[3], fmaf(a, f1.y, o));
            best[4] = fmaxf(best[4], fmaf(a, f2.x, o));
            best[5] = fmaxf(best[5], fmaf(a, f2.y, o));
            best[6] = fmaxf(best[6], fmaf(a, f3.x, o));
            best[7] = fmaxf(best[7], fmaf(a, f3.y, o));
        }
    }
    float4* out = (float4*)(g_colpart + ((size_t)blockIdx.y * NB + n) * LL);
    out[m8 * 2]     = make_float4(best[0], best[1], best[2], best[3]);
    out[m8 * 2 + 1] = make_float4(best[4], best[5], best[6], best[7]);
}

__global__ __launch_bounds__(256) void finalize_n_kernel() {
    int n = blockIdx.x;
    float s = 0.f;
    for (int m = threadIdx.x; m < LL; m += 256) {
        float best = -INFINITY;
        #pragma unroll
        for (int sp = 0; sp < LSPLIT; sp++)
            best = fmaxf(best, g_colpart[((size_t)sp * NB + n) * LL + m]);
        s += fast_exp(best);
    }
    s = block_reduce_sum_256(s);
    if (threadIdx.x == 0)
        g_loss_n[n] = -logf(s * (1.0f / LL) + EPS_BAND);
}

__global__ void final_kernel(float* __restrict__ out) {
    float s = 0.f;
    #pragma unroll
    for (int n = 0; n < NB; n++) s += g_loss_n[n];
    out[0] = s * (1.0f / NB);
}

// ---------------- launch ------------------------------------------------------
extern "C" void kernel_launch(void* const* d_in, const int* in_sizes, int n_in,
                              void* d_out, int out_size) {
    const float* x = (const float*)d_in[0];
    const float* y = (const float*)d_in[1];
    float* out = (float*)d_out;

    cudaFuncSetAttribute(gemm_cos_mma, cudaFuncAttributeMaxDynamicSharedMemorySize,
                         SMEM_BYTES);

    ymu_kernel<<<CC, 256>>>(y);
    normalize_kernel<<<NL / 256, 256>>>(x, 0);
    normalize_kernel<<<NL / 256, 256>>>(y, 1);
    gemm_cos_mma<<<dim3(LL / TN, LL / TM, NB), 512, SMEM_BYTES>>>();
    row_pass_kernel<<<NL, 256>>>();
    col_pass_kernel<<<dim3(LL / 2048, LSPLIT, NB), 256>>>();
    finalize_n_kernel<<<NB, 256>>>();
    final_kernel<<<1, 1>>>(out);
}

// round 13
// speedup vs baseline: 1.2292x; 1.2292x over previous
#include <cuda_runtime.h>
#include <cuda_fp16.h>
#include <math.h>
#include <stdint.h>

#define NB 8
#define CC 128
#define LL 4096
#define NL (NB * LL)          // 32768
#define LSPLIT 8
#define EPS_BAND 1e-5f

// GEMM tile
#define TM 128
#define TN 256
#define SSH 136                                   // padded row stride in halves
#define A_HALFS (TM * SSH)                        // 17408
#define B_HALFS (TN * SSH)                        // 34816
#define SMEM_BYTES ((A_HALFS + B_HALFS) * 2)      // 104448
#define STG_STRIDE 132                            // staging stride in words

// ---------------- scratch (device globals; device-code references only) ------
__device__ float  g_ymu[CC];
__device__ __half g_xh[(size_t)NB * LL * CC];          // K-major [n][l][c] fp16
__device__ __half g_yh[(size_t)NB * LL * CC];
__device__ __half g_cosh[(size_t)NB * LL * LL];        // 268 MB fp16 cos
__device__ float  g_alpha[NL];
__device__ float  g_off[NL];
__device__ float  g_colpart[(size_t)LSPLIT * NB * LL];
__device__ float  g_loss_n[NB];

// ---------------- asm helpers --------------------------------------------------
__device__ __forceinline__ uint32_t smem_u32(const void* p) {
    uint32_t a;
    asm("{ .reg .u64 t; cvta.to.shared.u64 t, %1; cvt.u32.u64 %0, t; }" : "=r"(a) : "l"(p));
    return a;
}
#define CP_ASYNC16(sa, gp) \
    asm volatile("cp.async.cg.shared.global [%0], [%1], 16;" :: "r"(sa), "l"(gp))
#define CP_COMMIT() asm volatile("cp.async.commit_group;" ::: "memory")

__device__ __forceinline__ void mma_f16(float* c, const uint32_t* a, const uint32_t* b) {
    asm volatile(
        "mma.sync.aligned.m16n8k16.row.col.f32.f16.f16.f32 "
        "{%0,%1,%2,%3}, {%4,%5,%6,%7}, {%8,%9}, {%0,%1,%2,%3};"
        : "+f"(c[0]), "+f"(c[1]), "+f"(c[2]), "+f"(c[3])
        : "r"(a[0]), "r"(a[1]), "r"(a[2]), "r"(a[3]), "r"(b[0]), "r"(b[1]));
}

__device__ __forceinline__ float fast_exp(float x) {
    float y = x * 1.4426950408889634f;
    float t = y + 12582912.0f;
    int   n = __float_as_int(t) - 0x4B400000;
    float f = y - (t - 12582912.0f);
    float p =            1.3333558146e-3f;
    p = fmaf(p, f, 9.6181291071e-3f);
    p = fmaf(p, f, 5.5504108664e-2f);
    p = fmaf(p, f, 2.4022650696e-1f);
    p = fmaf(p, f, 6.9314718056e-1f);
    p = fmaf(p, f, 1.0f);
    return __int_as_float(__float_as_int(p) + (n << 23));
}

__device__ __forceinline__ float block_reduce_sum_256(float v) {
    __shared__ float sh[8];
    int lane = threadIdx.x & 31, w = threadIdx.x >> 5;
    #pragma unroll
    for (int o = 16; o; o >>= 1) v += __shfl_xor_sync(0xffffffffu, v, o);
    if (lane == 0) sh[w] = v;
    __syncthreads();
    if (w == 0) {
        v = (lane < 8) ? sh[lane] : 0.f;
        #pragma unroll
        for (int o = 4; o; o >>= 1) v += __shfl_xor_sync(0xffffffffu, v, o);
    }
    return v;
}
__device__ __forceinline__ float block_reduce_max_256(float v) {
    __shared__ float shm[8];
    int lane = threadIdx.x & 31, w = threadIdx.x >> 5;
    #pragma unroll
    for (int o = 16; o; o >>= 1) v = fmaxf(v, __shfl_xor_sync(0xffffffffu, v, o));
    if (lane == 0) shm[w] = v;
    __syncthreads();
    if (w == 0) {
        v = (lane < 8) ? shm[lane] : -INFINITY;
        #pragma unroll
        for (int o = 4; o; o >>= 1) v = fmaxf(v, __shfl_xor_sync(0xffffffffu, v, o));
    }
    return v;
}

// ---------------- kernels ------------------------------------------------------

__global__ __launch_bounds__(256) void ymu_kernel(const float* __restrict__ y) {
    int c = blockIdx.x;
    float s = 0.f;
    for (int i = threadIdx.x; i < NB * LL; i += 256) {
        int n = i >> 12, l = i & (LL - 1);
        s += y[(size_t)n * CC * LL + (size_t)c * LL + l];
    }
    s = block_reduce_sum_256(s);
    if (threadIdx.x == 0) g_ymu[c] = s * (1.0f / (NB * LL));
}

// Center + L2-normalize; K-major [n][l][c] fp16 output.
__global__ __launch_bounds__(256) void normalize_kernel(const float* __restrict__ src,
                                                        int dst_sel) {
    __half* __restrict__ dst = dst_sel ? g_yh : g_xh;
    __shared__ float mu[CC];
    if (threadIdx.x < CC) mu[threadIdx.x] = g_ymu[threadIdx.x];
    __syncthreads();
    int idx = blockIdx.x * 256 + threadIdx.x;  // n*L + l
    int n = idx >> 12, l = idx & (LL - 1);
    size_t base = (size_t)n * CC * LL + l;
    float ss = 0.f;
    #pragma unroll 8
    for (int c = 0; c < CC; c++) {
        float v = src[base + (size_t)c * LL] - mu[c];
        ss += v * v;
    }
    float r = 1.0f / fmaxf(sqrtf(ss), 1e-12f);
    uint4* drow = (uint4*)(dst + ((size_t)n * LL + l) * CC);
    #pragma unroll 2
    for (int c0 = 0; c0 < CC; c0 += 8) {
        __half2 p0 = __floats2half2_rn((src[base + (size_t)(c0 + 0) * LL] - mu[c0 + 0]) * r,
                                       (src[base + (size_t)(c0 + 1) * LL] - mu[c0 + 1]) * r);
        __half2 p1 = __floats2half2_rn((src[base + (size_t)(c0 + 2) * LL] - mu[c0 + 2]) * r,
                                       (src[base + (size_t)(c0 + 3) * LL] - mu[c0 + 3]) * r);
        __half2 p2 = __floats2half2_rn((src[base + (size_t)(c0 + 4) * LL] - mu[c0 + 4]) * r,
                                       (src[base + (size_t)(c0 + 5) * LL] - mu[c0 + 5]) * r);
        __half2 p3 = __floats2half2_rn((src[base + (size_t)(c0 + 6) * LL] - mu[c0 + 6]) * r,
                                       (src[base + (size_t)(c0 + 7) * LL] - mu[c0 + 7]) * r);
        uint4 o;
        o.x = *(uint32_t*)&p0; o.y = *(uint32_t*)&p1;
        o.z = *(uint32_t*)&p2; o.w = *(uint32_t*)&p3;
        drow[c0 >> 3] = o;
    }
}

// fp16 mma.sync GEMM: TM x TN tile, K=128, cp.async 4-stage K-pipeline (K=32 each).
// Scalar LDS fragment loads (R10-proven) + smem-staged coalesced fp16 epilogue.
__global__ __launch_bounds__(512, 1) void gemm_cos_mma() {
    extern __shared__ __half smh[];
    uint32_t* smu = (uint32_t*)smh;
    uint32_t sbase = smem_u32(smh);
    int tid = threadIdx.x;
    int w = tid >> 5, lane = tid & 31;
    int g = lane >> 2, t = lane & 3;
    int wm = w & 3, wn = w >> 2;
    int n = blockIdx.z, l0 = blockIdx.y * TM, m0 = blockIdx.x * TN;

    const __half* Agp = g_xh + ((size_t)n * LL + l0) * CC;
    const __half* Bgp = g_yh + ((size_t)n * LL + m0) * CC;

    // Producer: 4 cp.async groups, stage s covers K columns [32s, 32s+32).
    #pragma unroll
    for (int s = 0; s < 4; s++) {
        {   // A: 128 rows x 4 16B-chunks = 512
            int r = tid >> 2, q = tid & 3;
            uint32_t sa = sbase + (uint32_t)(r * SSH + s * 32 + q * 8) * 2;
            CP_ASYNC16(sa, Agp + r * CC + s * 32 + q * 8);
        }
        #pragma unroll
        for (int it = 0; it < 2; it++) {  // B: 256 rows x 4 chunks = 1024
            int id = tid + it * 512; int r = id >> 2, q = id & 3;
            uint32_t sa = sbase + (uint32_t)(A_HALFS + r * SSH + s * 32 + q * 8) * 2;
            CP_ASYNC16(sa, Bgp + r * CC + s * 32 + q * 8);
        }
        CP_COMMIT();
    }

    float acc[2][8][4];
    #pragma unroll
    for (int mt = 0; mt < 2; mt++)
        #pragma unroll
        for (int nt = 0; nt < 8; nt++)
            #pragma unroll
            for (int j = 0; j < 4; j++) acc[mt][nt][j] = 0.f;

    const __half* Ah = smh;
    const __half* Bh = smh + A_HALFS;

    #pragma unroll
    for (int s = 0; s < 4; s++) {
        if      (s == 0) asm volatile("cp.async.wait_group 3;" ::: "memory");
        else if (s == 1) asm volatile("cp.async.wait_group 2;" ::: "memory");
        else if (s == 2) asm volatile("cp.async.wait_group 1;" ::: "memory");
        else             asm volatile("cp.async.wait_group 0;" ::: "memory");
        __syncthreads();
        #pragma unroll
        for (int k2 = 0; k2 < 2; k2++) {
            int kh = (s * 2 + k2) * 16;
            uint32_t a[2][4], b[8][2];
            #pragma unroll
            for (int mt = 0; mt < 2; mt++) {
                const __half* rp = Ah + (wm * 32 + mt * 16 + g) * SSH + kh + 2 * t;
                a[mt][0] = *(const uint32_t*)rp;
                a[mt][1] = *(const uint32_t*)(rp + 8 * SSH);
                a[mt][2] = *(const uint32_t*)(rp + 8);
                a[mt][3] = *(const uint32_t*)(rp + 8 * SSH + 8);
            }
            #pragma unroll
            for (int nt = 0; nt < 8; nt++) {
                const __half* rp = Bh + (wn * 64 + nt * 8 + g) * SSH + kh + 2 * t;
                b[nt][0] = *(const uint32_t*)rp;
                b[nt][1] = *(const uint32_t*)(rp + 8);
            }
            #pragma unroll
            for (int mt = 0; mt < 2; mt++)
                #pragma unroll
                for (int nt = 0; nt < 8; nt++)
                    mma_f16(acc[mt][nt], a[mt], b[nt]);
        }
    }

    // Epilogue: stage fp16 tile in smem (reuse operand region), coalesced STG.
    __syncthreads();
    #pragma unroll
    for (int mt = 0; mt < 2; mt++) {
        #pragma unroll
        for (int nt = 0; nt < 8; nt++) {
            int off = wn * 32 + nt * 4 + t;
            int r0  = wm * 32 + mt * 16 + g;
            __half2 h01 = __floats2half2_rn(acc[mt][nt][0], acc[mt][nt][1]);
            __half2 h23 = __floats2half2_rn(acc[mt][nt][2], acc[mt][nt][3]);
            smu[r0 * STG_STRIDE + off]       = *(uint32_t*)&h01;
            smu[(r0 + 8) * STG_STRIDE + off] = *(uint32_t*)&h23;
        }
    }
    __syncthreads();
    __half* dstbase = g_cosh + ((size_t)n * LL + l0) * LL + m0;
    #pragma unroll
    for (int it = 0; it < (TM * 32) / 512; it++) {
        int id = tid + it * 512; int r = id >> 5, q = id & 31;
        uint4 v = *(uint4*)(smu + r * STG_STRIDE + q * 4);
        *(uint4*)(dstbase + (size_t)r * LL + q * 8) = v;
    }
}

// Per row: rowmax -> alpha; Z = sum exp(alpha*(cos-1)); fp16 row read.
__global__ __launch_bounds__(256) void row_pass_kernel() {
    __shared__ float s_bcast;
    int row = blockIdx.x;  // n*L + l
    const uint4* cr = (const uint4*)(g_cosh + (size_t)row * LL);
    int t = threadIdx.x;

    uint4 u[2];
    u[0] = cr[t * 2];
    u[1] = cr[t * 2 + 1];

    float2 f[8];
    #pragma unroll
    for (int i = 0; i < 2; i++) {
        f[i * 4 + 0] = __half22float2(*(__half2*)&u[i].x);
        f[i * 4 + 1] = __half22float2(*(__half2*)&u[i].y);
        f[i * 4 + 2] = __half22float2(*(__half2*)&u[i].z);
        f[i * 4 + 3] = __half22float2(*(__half2*)&u[i].w);
    }
    float mx = -INFINITY;
    #pragma unroll
    for (int i = 0; i < 8; i++) mx = fmaxf(mx, fmaxf(f[i].x, f[i].y));
    mx = block_reduce_max_256(mx);
    if (threadIdx.x == 0) s_bcast = mx;
    __syncthreads();
    float rowmax = s_bcast;

    float dmin  = 1.0f - rowmax;
    float alpha = 2.0f / (dmin + EPS_BAND);

    float s = 0.f;
    #pragma unroll
    for (int i = 0; i < 8; i++) {
        s += fast_exp(alpha * (f[i].x - 1.0f));
        s += fast_exp(alpha * (f[i].y - 1.0f));
    }
    s = block_reduce_sum_256(s);
    if (threadIdx.x == 0) {
        g_alpha[row] = alpha;
        g_off[row]   = -alpha - logf(s);
    }
}

// Column pass over fp16 cos: partial max of (alpha_l*cos + off_l), half2/thread.
__global__ __launch_bounds__(256) void col_pass_kernel() {
    int n = blockIdx.z;
    int m2 = blockIdx.x * 256 + threadIdx.x;       // half2 index (grid.x = LL/512)
    int lbeg = blockIdx.y * (LL / LSPLIT);
    __shared__ float sA[128], sO[128];
    const __half* Cp = g_cosh + (size_t)n * LL * LL;
    float bx = -INFINITY, by = -INFINITY;
    for (int c = 0; c < (LL / LSPLIT) / 128; c++) {
        int lb = lbeg + c * 128;
        __syncthreads();
        if (threadIdx.x < 128) {
            sA[threadIdx.x] = g_alpha[n * LL + lb + threadIdx.x];
            sO[threadIdx.x] = g_off[n * LL + lb + threadIdx.x];
        }
        __syncthreads();
        #pragma unroll 8
        for (int li = 0; li < 128; li++) {
            __half2 hp = ((const __half2*)(Cp + (size_t)(lb + li) * LL))[m2];
            float2 fv = __half22float2(hp);
            bx = fmaxf(bx, fmaf(sA[li], fv.x, sO[li]));
            by = fmaxf(by, fmaf(sA[li], fv.y, sO[li]));
        }
    }
    float* out = g_colpart + ((size_t)blockIdx.y * NB + n) * LL;
    out[2 * m2]     = bx;
    out[2 * m2 + 1] = by;
}

__global__ __launch_bounds__(256) void finalize_n_kernel() {
    int n = blockIdx.x;
    float s = 0.f;
    for (int m = threadIdx.x; m < LL; m += 256) {
        float best = -INFINITY;
        #pragma unroll
        for (int sp = 0; sp < LSPLIT; sp++)
            best = fmaxf(best, g_colpart[((size_t)sp * NB + n) * LL + m]);
        s += fast_exp(best);
    }
    s = block_reduce_sum_256(s);
    if (threadIdx.x == 0)
        g_loss_n[n] = -logf(s * (1.0f / LL) + EPS_BAND);
}

__global__ void final_kernel(float* __restrict__ out) {
    float s = 0.f;
    #pragma unroll
    for (int n = 0; n < NB; n++) s += g_loss_n[n];
    out[0] = s * (1.0f / NB);
}

// ---------------- launch ------------------------------------------------------
extern "C" void kernel_launch(void* const* d_in, const int* in_sizes, int n_in,
                              void* d_out, int out_size) {
    const float* x = (const float*)d_in[0];
    const float* y = (const float*)d_in[1];
    float* out = (float*)d_out;

    cudaFuncSetAttribute(gemm_cos_mma, cudaFuncAttributeMaxDynamicSharedMemorySize,
                         SMEM_BYTES);

    ymu_kernel<<<CC, 256>>>(y);
    normalize_kernel<<<NL / 256, 256>>>(x, 0);
    normalize_kernel<<<NL / 256, 256>>>(y, 1);
    gemm_cos_mma<<<dim3(LL / TN, LL / TM, NB), 512, SMEM_BYTES>>>();
    row_pass_kernel<<<NL, 256>>>();
    col_pass_kernel<<<dim3(LL / 512, LSPLIT, NB), 256>>>();
    finalize_n_kernel<<<NB, 256>>>();
    final_kernel<<<1, 1>>>(out);
}

// round 15
// speedup vs baseline: 1.2408x; 1.0094x over previous
#include <cuda_runtime.h>
#include <cuda_fp16.h>
#include <math.h>
#include <stdint.h>

#define NB 8
#define CC 128
#define LL 4096
#define NL (NB * LL)          // 32768
#define LSPLIT 8
#define EPS_BAND 1e-5f

// GEMM tile
#define TM 128
#define TN 256
#define SSH 136                                   // padded row stride in halves
#define A_HALFS (TM * SSH)                        // 17408
#define B_HALFS (TN * SSH)                        // 34816
#define SMEM_BYTES ((A_HALFS + B_HALFS) * 2)      // 104448
#define STG_STRIDE 132                            // staging stride in words

// ---------------- scratch (device globals; device-code references only) ------
__device__ float  g_ymu[CC];
__device__ __half g_xh[(size_t)NB * LL * CC];          // K-major [n][l][c] fp16
__device__ __half g_yh[(size_t)NB * LL * CC];
__device__ __half g_cosh[(size_t)NB * LL * LL];        // 268 MB fp16 cos
__device__ float  g_alpha[NL];
__device__ float  g_off[NL];
__device__ float  g_colpart[(size_t)LSPLIT * NB * LL];
__device__ float  g_loss_n[NB];

// ---------------- asm helpers --------------------------------------------------
__device__ __forceinline__ uint32_t smem_u32(const void* p) {
    uint32_t a;
    asm("{ .reg .u64 t; cvta.to.shared.u64 t, %1; cvt.u32.u64 %0, t; }" : "=r"(a) : "l"(p));
    return a;
}
#define CP_ASYNC16(sa, gp) \
    asm volatile("cp.async.cg.shared.global [%0], [%1], 16;" :: "r"(sa), "l"(gp))
#define CP_COMMIT() asm volatile("cp.async.commit_group;" ::: "memory")

#define LDSM4(R, addr) \
    asm volatile("ldmatrix.sync.aligned.m8n8.x4.shared.b16 {%0,%1,%2,%3}, [%4];" \
        : "=r"((R)[0]), "=r"((R)[1]), "=r"((R)[2]), "=r"((R)[3]) : "r"(addr))

__device__ __forceinline__ void mma_f16(float* c, const uint32_t* a, const uint32_t* b) {
    asm volatile(
        "mma.sync.aligned.m16n8k16.row.col.f32.f16.f16.f32 "
        "{%0,%1,%2,%3}, {%4,%5,%6,%7}, {%8,%9}, {%0,%1,%2,%3};"
        : "+f"(c[0]), "+f"(c[1]), "+f"(c[2]), "+f"(c[3])
        : "r"(a[0]), "r"(a[1]), "r"(a[2]), "r"(a[3]), "r"(b[0]), "r"(b[1]));
}

__device__ __forceinline__ float fast_exp(float x) {
    float y = x * 1.4426950408889634f;
    float t = y + 12582912.0f;
    int   n = __float_as_int(t) - 0x4B400000;
    float f = y - (t - 12582912.0f);
    float p =            1.3333558146e-3f;
    p = fmaf(p, f, 9.6181291071e-3f);
    p = fmaf(p, f, 5.5504108664e-2f);
    p = fmaf(p, f, 2.4022650696e-1f);
    p = fmaf(p, f, 6.9314718056e-1f);
    p = fmaf(p, f, 1.0f);
    return __int_as_float(__float_as_int(p) + (n << 23));
}

__device__ __forceinline__ float block_reduce_sum_256(float v) {
    __shared__ float sh[8];
    int lane = threadIdx.x & 31, w = threadIdx.x >> 5;
    #pragma unroll
    for (int o = 16; o; o >>= 1) v += __shfl_xor_sync(0xffffffffu, v, o);
    if (lane == 0) sh[w] = v;
    __syncthreads();
    if (w == 0) {
        v = (lane < 8) ? sh[lane] : 0.f;
        #pragma unroll
        for (int o = 4; o; o >>= 1) v += __shfl_xor_sync(0xffffffffu, v, o);
    }
    return v;
}
__device__ __forceinline__ float block_reduce_max_256(float v) {
    __shared__ float shm[8];
    int lane = threadIdx.x & 31, w = threadIdx.x >> 5;
    #pragma unroll
    for (int o = 16; o; o >>= 1) v = fmaxf(v, __shfl_xor_sync(0xffffffffu, v, o));
    if (lane == 0) shm[w] = v;
    __syncthreads();
    if (w == 0) {
        v = (lane < 8) ? shm[lane] : -INFINITY;
        #pragma unroll
        for (int o = 4; o; o >>= 1) v = fmaxf(v, __shfl_xor_sync(0xffffffffu, v, o));
    }
    return v;
}

// ---------------- kernels ------------------------------------------------------

__global__ __launch_bounds__(256) void ymu_kernel(const float* __restrict__ y) {
    int c = blockIdx.x;
    float s = 0.f;
    for (int i = threadIdx.x; i < NB * LL; i += 256) {
        int n = i >> 12, l = i & (LL - 1);
        s += y[(size_t)n * CC * LL + (size_t)c * LL + l];
    }
    s = block_reduce_sum_256(s);
    if (threadIdx.x == 0) g_ymu[c] = s * (1.0f / (NB * LL));
}

// Center + L2-normalize; K-major [n][l][c] fp16 output.
__global__ __launch_bounds__(256) void normalize_kernel(const float* __restrict__ src,
                                                        int dst_sel) {
    __half* __restrict__ dst = dst_sel ? g_yh : g_xh;
    __shared__ float mu[CC];
    if (threadIdx.x < CC) mu[threadIdx.x] = g_ymu[threadIdx.x];
    __syncthreads();
    int idx = blockIdx.x * 256 + threadIdx.x;  // n*L + l
    int n = idx >> 12, l = idx & (LL - 1);
    size_t base = (size_t)n * CC * LL + l;
    float ss = 0.f;
    #pragma unroll 8
    for (int c = 0; c < CC; c++) {
        float v = src[base + (size_t)c * LL] - mu[c];
        ss += v * v;
    }
    float r = 1.0f / fmaxf(sqrtf(ss), 1e-12f);
    uint4* drow = (uint4*)(dst + ((size_t)n * LL + l) * CC);
    #pragma unroll 2
    for (int c0 = 0; c0 < CC; c0 += 8) {
        __half2 p0 = __floats2half2_rn((src[base + (size_t)(c0 + 0) * LL] - mu[c0 + 0]) * r,
                                       (src[base + (size_t)(c0 + 1) * LL] - mu[c0 + 1]) * r);
        __half2 p1 = __floats2half2_rn((src[base + (size_t)(c0 + 2) * LL] - mu[c0 + 2]) * r,
                                       (src[base + (size_t)(c0 + 3) * LL] - mu[c0 + 3]) * r);
        __half2 p2 = __floats2half2_rn((src[base + (size_t)(c0 + 4) * LL] - mu[c0 + 4]) * r,
                                       (src[base + (size_t)(c0 + 5) * LL] - mu[c0 + 5]) * r);
        __half2 p3 = __floats2half2_rn((src[base + (size_t)(c0 + 6) * LL] - mu[c0 + 6]) * r,
                                       (src[base + (size_t)(c0 + 7) * LL] - mu[c0 + 7]) * r);
        uint4 o;
        o.x = *(uint32_t*)&p0; o.y = *(uint32_t*)&p1;
        o.z = *(uint32_t*)&p2; o.w = *(uint32_t*)&p3;
        drow[c0 >> 3] = o;
    }
}

// fp16 mma.sync GEMM: TM x TN, K=128, cp.async 4-stage K-pipeline,
// ldmatrix.x4 fragment loads, smem-staged coalesced fp16 epilogue.
__global__ __launch_bounds__(512, 1) void gemm_cos_mma() {
    extern __shared__ __half smh[];
    uint32_t* smu = (uint32_t*)smh;
    uint32_t sbase = smem_u32(smh);
    int tid = threadIdx.x;
    int w = tid >> 5, lane = tid & 31;
    int g = lane >> 2, t = lane & 3;
    int wm = w & 3, wn = w >> 2;
    int n = blockIdx.z, l0 = blockIdx.y * TM, m0 = blockIdx.x * TN;

    const __half* Agp = g_xh + ((size_t)n * LL + l0) * CC;
    const __half* Bgp = g_yh + ((size_t)n * LL + m0) * CC;

    // Producer: 4 cp.async groups, stage s covers K columns [32s, 32s+32).
    #pragma unroll
    for (int s = 0; s < 4; s++) {
        {   // A: 128 rows x 4 16B-chunks = 512
            int r = tid >> 2, q = tid & 3;
            uint32_t sa = sbase + (uint32_t)(r * SSH + s * 32 + q * 8) * 2;
            CP_ASYNC16(sa, Agp + r * CC + s * 32 + q * 8);
        }
        #pragma unroll
        for (int it = 0; it < 2; it++) {  // B: 256 rows x 4 chunks = 1024
            int id = tid + it * 512; int r = id >> 2, q = id & 3;
            uint32_t sa = sbase + (uint32_t)(A_HALFS + r * SSH + s * 32 + q * 8) * 2;
            CP_ASYNC16(sa, Bgp + r * CC + s * 32 + q * 8);
        }
        CP_COMMIT();
    }

    // ldmatrix per-lane base addresses (bytes). Validated in R11 (rel_err identical).
    uint32_t a_base = sbase + (uint32_t)((wm * 32 + ((lane >> 3) & 1) * 8 + (lane & 7)) * SSH
                                         + ((lane >> 4) & 1) * 8) * 2;
    uint32_t b_base = sbase + (uint32_t)(A_HALFS
                                         + (wn * 64 + ((lane >> 4) & 1) * 8 + (lane & 7)) * SSH
                                         + ((lane >> 3) & 1) * 8) * 2;

    float acc[2][8][4];
    #pragma unroll
    for (int mt = 0; mt < 2; mt++)
        #pragma unroll
        for (int nt = 0; nt < 8; nt++)
            #pragma unroll
            for (int j = 0; j < 4; j++) acc[mt][nt][j] = 0.f;

    #pragma unroll
    for (int s = 0; s < 4; s++) {
        if      (s == 0) asm volatile("cp.async.wait_group 3;" ::: "memory");
        else if (s == 1) asm volatile("cp.async.wait_group 2;" ::: "memory");
        else if (s == 2) asm volatile("cp.async.wait_group 1;" ::: "memory");
        else             asm volatile("cp.async.wait_group 0;" ::: "memory");
        __syncthreads();
        #pragma unroll
        for (int k2 = 0; k2 < 2; k2++) {
            int ks = s * 2 + k2;               // k16 chunk; byte col offset = ks*32
            uint32_t a[2][4], bb[4][4];
            #pragma unroll
            for (int mt = 0; mt < 2; mt++)
                LDSM4(a[mt], a_base + (uint32_t)(mt * 16 * SSH * 2 + ks * 32));
            #pragma unroll
            for (int np = 0; np < 4; np++)
                LDSM4(bb[np], b_base + (uint32_t)(np * 16 * SSH * 2 + ks * 32));
            #pragma unroll
            for (int mt = 0; mt < 2; mt++)
                #pragma unroll
                for (int np = 0; np < 4; np++) {
                    mma_f16(acc[mt][2 * np],     a[mt], &bb[np][0]);
                    mma_f16(acc[mt][2 * np + 1], a[mt], &bb[np][2]);
                }
        }
    }

    // Epilogue: stage fp16 tile in smem (reuse operand region), coalesced STG.
    __syncthreads();
    #pragma unroll
    for (int mt = 0; mt < 2; mt++) {
        #pragma unroll
        for (int nt = 0; nt < 8; nt++) {
            int off = wn * 32 + nt * 4 + t;
            int r0  = wm * 32 + mt * 16 + g;
            __half2 h01 = __floats2half2_rn(acc[mt][nt][0], acc[mt][nt][1]);
            __half2 h23 = __floats2half2_rn(acc[mt][nt][2], acc[mt][nt][3]);
            smu[r0 * STG_STRIDE + off]       = *(uint32_t*)&h01;
            smu[(r0 + 8) * STG_STRIDE + off] = *(uint32_t*)&h23;
        }
    }
    __syncthreads();
    __half* dstbase = g_cosh + ((size_t)n * LL + l0) * LL + m0;
    #pragma unroll
    for (int it = 0; it < (TM * 32) / 512; it++) {
        int id = tid + it * 512; int r = id >> 5, q = id & 31;
        uint4 v = *(uint4*)(smu + r * STG_STRIDE + q * 4);
        *(uint4*)(dstbase + (size_t)r * LL + q * 8) = v;
    }
}

// Per row: rowmax -> alpha; Z = sum exp(alpha*(cos-1)); fp16 row read.
__global__ __launch_bounds__(256) void row_pass_kernel() {
    __shared__ float s_bcast;
    int row = blockIdx.x;  // n*L + l
    const uint4* cr = (const uint4*)(g_cosh + (size_t)row * LL);
    int t = threadIdx.x;

    uint4 u[2];
    u[0] = cr[t * 2];
    u[1] = cr[t * 2 + 1];

    float2 f[8];
    #pragma unroll
    for (int i = 0; i < 2; i++) {
        f[i * 4 + 0] = __half22float2(*(__half2*)&u[i].x);
        f[i * 4 + 1] = __half22float2(*(__half2*)&u[i].y);
        f[i * 4 + 2] = __half22float2(*(__half2*)&u[i].z);
        f[i * 4 + 3] = __half22float2(*(__half2*)&u[i].w);
    }
    float mx = -INFINITY;
    #pragma unroll
    for (int i = 0; i < 8; i++) mx = fmaxf(mx, fmaxf(f[i].x, f[i].y));
    mx = block_reduce_max_256(mx);
    if (threadIdx.x == 0) s_bcast = mx;
    __syncthreads();
    float rowmax = s_bcast;

    float dmin  = 1.0f - rowmax;
    float alpha = 2.0f / (dmin + EPS_BAND);

    float s = 0.f;
    #pragma unroll
    for (int i = 0; i < 8; i++) {
        s += fast_exp(alpha * (f[i].x - 1.0f));
        s += fast_exp(alpha * (f[i].y - 1.0f));
    }
    s = block_reduce_sum_256(s);
    if (threadIdx.x == 0) {
        g_alpha[row] = alpha;
        g_off[row]   = -alpha - logf(s);
    }
}

// Column pass over fp16 cos: partial max of (alpha_l*cos + off_l), half2/thread.
__global__ __launch_bounds__(256) void col_pass_kernel() {
    int n = blockIdx.z;
    int m2 = blockIdx.x * 256 + threadIdx.x;       // half2 index (grid.x = LL/512)
    int lbeg = blockIdx.y * (LL / LSPLIT);
    __shared__ float sA[128], sO[128];
    const __half* Cp = g_cosh + (size_t)n * LL * LL;
    float bx = -INFINITY, by = -INFINITY;
    for (int c = 0; c < (LL / LSPLIT) / 128; c++) {
        int lb = lbeg + c * 128;
        __syncthreads();
        if (threadIdx.x < 128) {
            sA[threadIdx.x] = g_alpha[n * LL + lb + threadIdx.x];
            sO[threadIdx.x] = g_off[n * LL + lb + threadIdx.x];
        }
        __syncthreads();
        #pragma unroll 8
        for (int li = 0; li < 128; li++) {
            __half2 hp = ((const __half2*)(Cp + (size_t)(lb + li) * LL))[m2];
            float2 fv = __half22float2(hp);
            bx = fmaxf(bx, fmaf(sA[li], fv.x, sO[li]));
            by = fmaxf(by, fmaf(sA[li], fv.y, sO[li]));
        }
    }
    float* out = g_colpart + ((size_t)blockIdx.y * NB + n) * LL;
    out[2 * m2]     = bx;
    out[2 * m2 + 1] = by;
}

__global__ __launch_bounds__(256) void finalize_n_kernel() {
    int n = blockIdx.x;
    float s = 0.f;
    for (int m = threadIdx.x; m < LL; m += 256) {
        float best = -INFINITY;
        #pragma unroll
        for (int sp = 0; sp < LSPLIT; sp++)
            best = fmaxf(best, g_colpart[((size_t)sp * NB + n) * LL + m]);
        s += fast_exp(best);
    }
    s = block_reduce_sum_256(s);
    if (threadIdx.x == 0)
        g_loss_n[n] = -logf(s * (1.0f / LL) + EPS_BAND);
}

__global__ void final_kernel(float* __restrict__ out) {
    float s = 0.f;
    #pragma unroll
    for (int n = 0; n < NB; n++) s += g_loss_n[n];
    out[0] = s * (1.0f / NB);
}

// ---------------- launch ------------------------------------------------------
extern "C" void kernel_launch(void* const* d_in, const int* in_sizes, int n_in,
                              void* d_out, int out_size) {
    const float* x = (const float*)d_in[0];
    const float* y = (const float*)d_in[1];
    float* out = (float*)d_out;

    cudaFuncSetAttribute(gemm_cos_mma, cudaFuncAttributeMaxDynamicSharedMemorySize,
                         SMEM_BYTES);

    ymu_kernel<<<CC, 256>>>(y);
    normalize_kernel<<<NL / 256, 256>>>(x, 0);
    normalize_kernel<<<NL / 256, 256>>>(y, 1);
    gemm_cos_mma<<<dim3(LL / TN, LL / TM, NB), 512, SMEM_BYTES>>>();
    row_pass_kernel<<<NL, 256>>>();
    col_pass_kernel<<<dim3(LL / 512, LSPLIT, NB), 256>>>();
    finalize_n_kernel<<<NB, 256>>>();
    final_kernel<<<1, 1>>>(out);
}

// round 17
// speedup vs baseline: 1.3002x; 1.0479x over previous
#include <cuda_runtime.h>
#include <cuda_fp16.h>
#include <math.h>
#include <stdint.h>

#define NB 8
#define CC 128
#define LL 4096
#define NL (NB * LL)          // 32768
#define LSPLIT 8
#define EPS_BAND 1e-5f

// GEMM tile (TM x TN per CTA, 256 threads, 2 CTAs/SM)
#define TM 128
#define TN 128
#define SSH 136                                   // padded row stride in halves
#define A_HALFS (TM * SSH)                        // 17408
#define B_HALFS (TN * SSH)                        // 17408
#define SMEM_BYTES ((A_HALFS + B_HALFS) * 2)      // 69632
#define STG_STRIDE 68                             // staging stride in words (64 + 4 pad)

// ---------------- scratch (device globals; device-code references only) ------
__device__ float  g_ymu[CC];
__device__ __half g_xh[(size_t)NB * LL * CC];          // K-major [n][l][c] fp16
__device__ __half g_yh[(size_t)NB * LL * CC];
__device__ __half g_cosh[(size_t)NB * LL * LL];        // 268 MB fp16 cos
__device__ float  g_alpha[NL];
__device__ float  g_off[NL];
__device__ float  g_colpart[(size_t)LSPLIT * NB * LL];
__device__ float  g_loss_n[NB];

// ---------------- asm helpers --------------------------------------------------
__device__ __forceinline__ uint32_t smem_u32(const void* p) {
    uint32_t a;
    asm("{ .reg .u64 t; cvta.to.shared.u64 t, %1; cvt.u32.u64 %0, t; }" : "=r"(a) : "l"(p));
    return a;
}
#define CP_ASYNC16(sa, gp) \
    asm volatile("cp.async.cg.shared.global [%0], [%1], 16;" :: "r"(sa), "l"(gp))
#define CP_COMMIT() asm volatile("cp.async.commit_group;" ::: "memory")

#define LDSM4(R, addr) \
    asm volatile("ldmatrix.sync.aligned.m8n8.x4.shared.b16 {%0,%1,%2,%3}, [%4];" \
        : "=r"((R)[0]), "=r"((R)[1]), "=r"((R)[2]), "=r"((R)[3]) : "r"(addr))

__device__ __forceinline__ void mma_f16(float* c, const uint32_t* a, const uint32_t* b) {
    asm volatile(
        "mma.sync.aligned.m16n8k16.row.col.f32.f16.f16.f32 "
        "{%0,%1,%2,%3}, {%4,%5,%6,%7}, {%8,%9}, {%0,%1,%2,%3};"
        : "+f"(c[0]), "+f"(c[1]), "+f"(c[2]), "+f"(c[3])
        : "r"(a[0]), "r"(a[1]), "r"(a[2]), "r"(a[3]), "r"(b[0]), "r"(b[1]));
}

__device__ __forceinline__ float fast_exp(float x) {
    float y = x * 1.4426950408889634f;
    float t = y + 12582912.0f;
    int   n = __float_as_int(t) - 0x4B400000;
    float f = y - (t - 12582912.0f);
    float p =            1.3333558146e-3f;
    p = fmaf(p, f, 9.6181291071e-3f);
    p = fmaf(p, f, 5.5504108664e-2f);
    p = fmaf(p, f, 2.4022650696e-1f);
    p = fmaf(p, f, 6.9314718056e-1f);
    p = fmaf(p, f, 1.0f);
    return __int_as_float(__float_as_int(p) + (n << 23));
}

__device__ __forceinline__ float block_reduce_sum_256(float v) {
    __shared__ float sh[8];
    int lane = threadIdx.x & 31, w = threadIdx.x >> 5;
    #pragma unroll
    for (int o = 16; o; o >>= 1) v += __shfl_xor_sync(0xffffffffu, v, o);
    if (lane == 0) sh[w] = v;
    __syncthreads();
    if (w == 0) {
        v = (lane < 8) ? sh[lane] : 0.f;
        #pragma unroll
        for (int o = 4; o; o >>= 1) v += __shfl_xor_sync(0xffffffffu, v, o);
    }
    return v;
}
__device__ __forceinline__ float block_reduce_max_256(float v) {
    __shared__ float shm[8];
    int lane = threadIdx.x & 31, w = threadIdx.x >> 5;
    #pragma unroll
    for (int o = 16; o; o >>= 1) v = fmaxf(v, __shfl_xor_sync(0xffffffffu, v, o));
    if (lane == 0) shm[w] = v;
    __syncthreads();
    if (w == 0) {
        v = (lane < 8) ? shm[lane] : -INFINITY;
        #pragma unroll
        for (int o = 4; o; o >>= 1) v = fmaxf(v, __shfl_xor_sync(0xffffffffu, v, o));
    }
    return v;
}

// ---------------- kernels ------------------------------------------------------

__global__ __launch_bounds__(256) void ymu_kernel(const float* __restrict__ y) {
    int c = blockIdx.x;
    float s = 0.f;
    for (int i = threadIdx.x; i < NB * LL; i += 256) {
        int n = i >> 12, l = i & (LL - 1);
        s += y[(size_t)n * CC * LL + (size_t)c * LL + l];
    }
    s = block_reduce_sum_256(s);
    if (threadIdx.x == 0) g_ymu[c] = s * (1.0f / (NB * LL));
}

// Center + L2-normalize; K-major [n][l][c] fp16 output.
__global__ __launch_bounds__(256) void normalize_kernel(const float* __restrict__ src,
                                                        int dst_sel) {
    __half* __restrict__ dst = dst_sel ? g_yh : g_xh;
    __shared__ float mu[CC];
    if (threadIdx.x < CC) mu[threadIdx.x] = g_ymu[threadIdx.x];
    __syncthreads();
    int idx = blockIdx.x * 256 + threadIdx.x;  // n*L + l
    int n = idx >> 12, l = idx & (LL - 1);
    size_t base = (size_t)n * CC * LL + l;
    float ss = 0.f;
    #pragma unroll 8
    for (int c = 0; c < CC; c++) {
        float v = src[base + (size_t)c * LL] - mu[c];
        ss += v * v;
    }
    float r = 1.0f / fmaxf(sqrtf(ss), 1e-12f);
    uint4* drow = (uint4*)(dst + ((size_t)n * LL + l) * CC);
    #pragma unroll 2
    for (int c0 = 0; c0 < CC; c0 += 8) {
        __half2 p0 = __floats2half2_rn((src[base + (size_t)(c0 + 0) * LL] - mu[c0 + 0]) * r,
                                       (src[base + (size_t)(c0 + 1) * LL] - mu[c0 + 1]) * r);
        __half2 p1 = __floats2half2_rn((src[base + (size_t)(c0 + 2) * LL] - mu[c0 + 2]) * r,
                                       (src[base + (size_t)(c0 + 3) * LL] - mu[c0 + 3]) * r);
        __half2 p2 = __floats2half2_rn((src[base + (size_t)(c0 + 4) * LL] - mu[c0 + 4]) * r,
                                       (src[base + (size_t)(c0 + 5) * LL] - mu[c0 + 5]) * r);
        __half2 p3 = __floats2half2_rn((src[base + (size_t)(c0 + 6) * LL] - mu[c0 + 6]) * r,
                                       (src[base + (size_t)(c0 + 7) * LL] - mu[c0 + 7]) * r);
        uint4 o;
        o.x = *(uint32_t*)&p0; o.y = *(uint32_t*)&p1;
        o.z = *(uint32_t*)&p2; o.w = *(uint32_t*)&p3;
        drow[c0 >> 3] = o;
    }
}

// fp16 mma.sync GEMM: TM=128 x TN=128, K=128, 256 threads, 2 CTAs/SM.
// 8 warps in 4(m) x 2(n) grid, each warp 32(m) x 64(n).
// cp.async 4-stage K-pipeline + ldmatrix.x4 + smem-staged coalesced epilogue.
__global__ __launch_bounds__(256, 2) void gemm_cos_mma() {
    extern __shared__ __half smh[];
    uint32_t* smu = (uint32_t*)smh;
    uint32_t sbase = smem_u32(smh);
    int tid = threadIdx.x;
    int w = tid >> 5, lane = tid & 31;
    int g = lane >> 2, t = lane & 3;
    int wm = w & 3, wn = w >> 2;                 // 4 x 2 warp grid
    int n = blockIdx.z, l0 = blockIdx.y * TM, m0 = blockIdx.x * TN;

    const __half* Agp = g_xh + ((size_t)n * LL + l0) * CC;
    const __half* Bgp = g_yh + ((size_t)n * LL + m0) * CC;

    // Producer: 4 cp.async groups; stage s covers K columns [32s, 32s+32).
    #pragma unroll
    for (int s = 0; s < 4; s++) {
        #pragma unroll
        for (int it = 0; it < 2; it++) {  // A: 128 rows x 4 16B-chunks = 512
            int id = tid + it * 256; int r = id >> 2, q = id & 3;
            uint32_t sa = sbase + (uint32_t)(r * SSH + s * 32 + q * 8) * 2;
            CP_ASYNC16(sa, Agp + r * CC + s * 32 + q * 8);
        }
        #pragma unroll
        for (int it = 0; it < 2; it++) {  // B: 128 rows x 4 chunks = 512
            int id = tid + it * 256; int r = id >> 2, q = id & 3;
            uint32_t sa = sbase + (uint32_t)(A_HALFS + r * SSH + s * 32 + q * 8) * 2;
            CP_ASYNC16(sa, Bgp + r * CC + s * 32 + q * 8);
        }
        CP_COMMIT();
    }

    // ldmatrix per-lane base addresses (bytes). Layout validated (rel_err identical).
    uint32_t a_base = sbase + (uint32_t)((wm * 32 + ((lane >> 3) & 1) * 8 + (lane & 7)) * SSH
                                         + ((lane >> 4) & 1) * 8) * 2;
    uint32_t b_base = sbase + (uint32_t)(A_HALFS
                                         + (wn * 64 + ((lane >> 4) & 1) * 8 + (lane & 7)) * SSH
                                         + ((lane >> 3) & 1) * 8) * 2;

    float acc[2][8][4];
    #pragma unroll
    for (int mt = 0; mt < 2; mt++)
        #pragma unroll
        for (int nt = 0; nt < 8; nt++)
            #pragma unroll
            for (int j = 0; j < 4; j++) acc[mt][nt][j] = 0.f;

    #pragma unroll
    for (int s = 0; s < 4; s++) {
        if      (s == 0) asm volatile("cp.async.wait_group 3;" ::: "memory");
        else if (s == 1) asm volatile("cp.async.wait_group 2;" ::: "memory");
        else if (s == 2) asm volatile("cp.async.wait_group 1;" ::: "memory");
        else             asm volatile("cp.async.wait_group 0;" ::: "memory");
        __syncthreads();
        #pragma unroll
        for (int k2 = 0; k2 < 2; k2++) {
            int ks = s * 2 + k2;               // k16 chunk; byte col offset = ks*32
            uint32_t a[2][4], bb[4][4];
            #pragma unroll
            for (int mt = 0; mt < 2; mt++)
                LDSM4(a[mt], a_base + (uint32_t)(mt * 16 * SSH * 2 + ks * 32));
            #pragma unroll
            for (int np = 0; np < 4; np++)
                LDSM4(bb[np], b_base + (uint32_t)(np * 16 * SSH * 2 + ks * 32));
            #pragma unroll
            for (int mt = 0; mt < 2; mt++)
                #pragma unroll
                for (int np = 0; np < 4; np++) {
                    mma_f16(acc[mt][2 * np],     a[mt], &bb[np][0]);
                    mma_f16(acc[mt][2 * np + 1], a[mt], &bb[np][2]);
                }
        }
    }

    // Epilogue: stage fp16 tile in smem (reuse operand region), coalesced STG.
    __syncthreads();
    #pragma unroll
    for (int mt = 0; mt < 2; mt++) {
        #pragma unroll
        for (int nt = 0; nt < 8; nt++) {
            int off = wn * 32 + nt * 4 + t;            // 0..63 words = 128 halves
            int r0  = wm * 32 + mt * 16 + g;
            __half2 h01 = __floats2half2_rn(acc[mt][nt][0], acc[mt][nt][1]);
            __half2 h23 = __floats2half2_rn(acc[mt][nt][2], acc[mt][nt][3]);
            smu[r0 * STG_STRIDE + off]       = *(uint32_t*)&h01;
            smu[(r0 + 8) * STG_STRIDE + off] = *(uint32_t*)&h23;
        }
    }
    __syncthreads();
    __half* dstbase = g_cosh + ((size_t)n * LL + l0) * LL + m0;
    #pragma unroll
    for (int it = 0; it < (TM * 16) / 256; it++) {     // 128 rows x 16 uint4
        int id = tid + it * 256; int r = id >> 4, q = id & 15;
        uint4 v = *(uint4*)(smu + r * STG_STRIDE + q * 4);
        *(uint4*)(dstbase + (size_t)r * LL + q * 8) = v;
    }
}

// Per row: rowmax -> alpha; Z = sum exp(alpha*(cos-1)); fp16 row read.
__global__ __launch_bounds__(256) void row_pass_kernel() {
    __shared__ float s_bcast;
    int row = blockIdx.x;  // n*L + l
    const uint4* cr = (const uint4*)(g_cosh + (size_t)row * LL);
    int t = threadIdx.x;

    uint4 u[2];
    u[0] = cr[t * 2];
    u[1] = cr[t * 2 + 1];

    float2 f[8];
    #pragma unroll
    for (int i = 0; i < 2; i++) {
        f[i * 4 + 0] = __half22float2(*(__half2*)&u[i].x);
        f[i * 4 + 1] = __half22float2(*(__half2*)&u[i].y);
        f[i * 4 + 2] = __half22float2(*(__half2*)&u[i].z);
        f[i * 4 + 3] = __half22float2(*(__half2*)&u[i].w);
    }
    float mx = -INFINITY;
    #pragma unroll
    for (int i = 0; i < 8; i++) mx = fmaxf(mx, fmaxf(f[i].x, f[i].y));
    mx = block_reduce_max_256(mx);
    if (threadIdx.x == 0) s_bcast = mx;
    __syncthreads();
    float rowmax = s_bcast;

    float dmin  = 1.0f - rowmax;
    float alpha = 2.0f / (dmin + EPS_BAND);

    float s = 0.f;
    #pragma unroll
    for (int i = 0; i < 8; i++) {
        s += fast_exp(alpha * (f[i].x - 1.0f));
        s += fast_exp(alpha * (f[i].y - 1.0f));
    }
    s = block_reduce_sum_256(s);
    if (threadIdx.x == 0) {
        g_alpha[row] = alpha;
        g_off[row]   = -alpha - logf(s);
    }
}

// Column pass over fp16 cos: partial max of (alpha_l*cos + off_l), half2/thread.
__global__ __launch_bounds__(256) void col_pass_kernel() {
    int n = blockIdx.z;
    int m2 = blockIdx.x * 256 + threadIdx.x;       // half2 index (grid.x = LL/512)
    int lbeg = blockIdx.y * (LL / LSPLIT);
    __shared__ float sA[128], sO[128];
    const __half* Cp = g_cosh + (size_t)n * LL * LL;
    float bx = -INFINITY, by = -INFINITY;
    for (int c = 0; c < (LL / LSPLIT) / 128; c++) {
        int lb = lbeg + c * 128;
        __syncthreads();
        if (threadIdx.x < 128) {
            sA[threadIdx.x] = g_alpha[n * LL + lb + threadIdx.x];
            sO[threadIdx.x] = g_off[n * LL + lb + threadIdx.x];
        }
        __syncthreads();
        #pragma unroll 8
        for (int li = 0; li < 128; li++) {
            __half2 hp = ((const __half2*)(Cp + (size_t)(lb + li) * LL))[m2];
            float2 fv = __half22float2(hp);
            bx = fmaxf(bx, fmaf(sA[li], fv.x, sO[li]));
            by = fmaxf(by, fmaf(sA[li], fv.y, sO[li]));
        }
    }
    float* out = g_colpart + ((size_t)blockIdx.y * NB + n) * LL;
    out[2 * m2]     = bx;
    out[2 * m2 + 1] = by;
}

__global__ __launch_bounds__(256) void finalize_n_kernel() {
    int n = blockIdx.x;
    float s = 0.f;
    for (int m = threadIdx.x; m < LL; m += 256) {
        float best = -INFINITY;
        #pragma unroll
        for (int sp = 0; sp < LSPLIT; sp++)
            best = fmaxf(best, g_colpart[((size_t)sp * NB + n) * LL + m]);
        s += fast_exp(best);
    }
    s = block_reduce_sum_256(s);
    if (threadIdx.x == 0)
        g_loss_n[n] = -logf(s * (1.0f / LL) + EPS_BAND);
}

__global__ void final_kernel(float* __restrict__ out) {
    float s = 0.f;
    #pragma unroll
    for (int n = 0; n < NB; n++) s += g_loss_n[n];
    out[0] = s * (1.0f / NB);
}

// ---------------- launch ------------------------------------------------------
extern "C" void kernel_launch(void* const* d_in, const int* in_sizes, int n_in,
                              void* d_out, int out_size) {
    const float* x = (const float*)d_in[0];
    const float* y = (const float*)d_in[1];
    float* out = (float*)d_out;

    cudaFuncSetAttribute(gemm_cos_mma, cudaFuncAttributeMaxDynamicSharedMemorySize,
                         SMEM_BYTES);

    ymu_kernel<<<CC, 256>>>(y);
    normalize_kernel<<<NL / 256, 256>>>(x, 0);
    normalize_kernel<<<NL / 256, 256>>>(y, 1);
    gemm_cos_mma<<<dim3(LL / TN, LL / TM, NB), 256, SMEM_BYTES>>>();
    row_pass_kernel<<<NL, 256>>>();
    col_pass_kernel<<<dim3(LL / 512, LSPLIT, NB), 256>>>();
    finalize_n_kernel<<<NB, 256>>>();
    final_kernel<<<1, 1>>>(out);
}